// round 1
// baseline (speedup 1.0000x reference)
#include <cuda_runtime.h>

#define N_NODES 100000
#define N_EDGES 1200000
#define F_IN 128
#define H 64
#define C 40

// ---------------- scratch (device globals; no allocs allowed) ----------------
__device__ int   g_is64;
__device__ int   g_deg[N_NODES];
__device__ float g_dinv[N_NODES];
__device__ int   g_src[N_EDGES];
__device__ int   g_dst[N_EDGES];
__device__ float g_norm[N_EDGES];
__device__ float g_h1[(size_t)N_NODES * H];   // x @ W1
__device__ float g_a1[(size_t)N_NODES * H];   // aggregated layer 1
__device__ float g_h2[(size_t)N_NODES * H];   // relu(a1+b1) @ W2

// ---------------- int64-vs-int32 edge_index detection ----------------
__global__ void k_detect(const void* ei) {
    if (threadIdx.x == 0 && blockIdx.x == 0) {
        const long long* p = (const long long*)ei;
        int ok = 1;
        for (int i = 0; i < 64; ++i) {
            long long v = p[i];
            if (v < 0 || v >= N_NODES) { ok = 0; break; }
        }
        g_is64 = ok;
    }
}

__device__ __forceinline__ int load_idx(const void* ei, int pos, int which) {
    if (g_is64) return (int)((const long long*)ei)[(size_t)which * N_EDGES + pos];
    return ((const int*)ei)[(size_t)which * N_EDGES + pos];
}

// ---------------- degree / norm ----------------
__global__ void k_zero_deg() {
    int i = blockIdx.x * blockDim.x + threadIdx.x;
    if (i < N_NODES) g_deg[i] = 0;
}

__global__ void k_hist(const void* __restrict__ ei) {
    int e = blockIdx.x * blockDim.x + threadIdx.x;
    if (e < N_EDGES) atomicAdd(&g_deg[load_idx(ei, e, 1)], 1);
}

__global__ void k_dinv() {
    int i = blockIdx.x * blockDim.x + threadIdx.x;
    if (i < N_NODES) g_dinv[i] = rsqrtf((float)(g_deg[i] + 1));  // +1 self-loop
}

__global__ void k_prep(const void* __restrict__ ei) {
    int e = blockIdx.x * blockDim.x + threadIdx.x;
    if (e < N_EDGES) {
        int s = load_idx(ei, e, 0);
        int d = load_idx(ei, e, 1);
        g_src[e] = s;
        g_dst[e] = d;
        g_norm[e] = g_dinv[s] * g_dinv[d];
    }
}

// ---------------- GEMM1: g_h1 = x @ W1  (100000x128 @ 128x64) ----------------
__global__ void __launch_bounds__(256) k_gemm1(const float* __restrict__ x,
                                               const float* __restrict__ W1) {
    __shared__ float Ws[F_IN * H];  // 32 KB
    int tid = threadIdx.x;
#pragma unroll
    for (int i = 0; i < (F_IN * H) / 256; ++i) Ws[tid + i * 256] = W1[tid + i * 256];
    __syncthreads();

    int r  = blockIdx.x * 16 + (tid >> 4);
    int cg = (tid & 15) << 2;
    const float4* xr = reinterpret_cast<const float4*>(x + (size_t)r * F_IN);

    float a0 = 0.f, a1 = 0.f, a2 = 0.f, a3 = 0.f;
#pragma unroll
    for (int k4 = 0; k4 < F_IN / 4; ++k4) {
        float4 xv = xr[k4];
        const float* wb = &Ws[(k4 * 4) * H + cg];
        float4 w0 = *(const float4*)(wb);
        float4 w1 = *(const float4*)(wb + H);
        float4 w2 = *(const float4*)(wb + 2 * H);
        float4 w3 = *(const float4*)(wb + 3 * H);
        a0 += xv.x * w0.x; a1 += xv.x * w0.y; a2 += xv.x * w0.z; a3 += xv.x * w0.w;
        a0 += xv.y * w1.x; a1 += xv.y * w1.y; a2 += xv.y * w1.z; a3 += xv.y * w1.w;
        a0 += xv.z * w2.x; a1 += xv.z * w2.y; a2 += xv.z * w2.z; a3 += xv.z * w2.w;
        a0 += xv.w * w3.x; a1 += xv.w * w3.y; a2 += xv.w * w3.z; a3 += xv.w * w3.w;
    }
    *(float4*)&g_h1[(size_t)r * H + cg] = make_float4(a0, a1, a2, a3);
}

// ---------------- self-loop init: a1 = dinv^2 * h1 ----------------
__global__ void k_self1() {
    int i = blockIdx.x * blockDim.x + threadIdx.x;
    if (i < N_NODES * H) {
        float di = g_dinv[i >> 6];
        g_a1[i] = di * di * g_h1[i];
    }
}

// ---------------- edge scatter 1: a1[dst] += norm * h1[src] ----------------
__global__ void __launch_bounds__(256) k_edge1() {
    int t = blockIdx.x * blockDim.x + threadIdx.x;
    int e = t >> 4;
    if (e >= N_EDGES) return;
    int lane = (t & 15) << 2;
    int s = g_src[e], d = g_dst[e];
    float nm = g_norm[e];
    float4 v = *(const float4*)(g_h1 + (size_t)s * H + lane);
    float* p = g_a1 + (size_t)d * H + lane;
    asm volatile("red.global.add.v4.f32 [%0], {%1,%2,%3,%4};" ::
                 "l"(p), "f"(v.x * nm), "f"(v.y * nm), "f"(v.z * nm), "f"(v.w * nm)
                 : "memory");
}

// ---------------- GEMM2: g_h2 = relu(a1 + b1) @ W2  (fused bias+relu) ----------------
__global__ void __launch_bounds__(256) k_gemm2(const float* __restrict__ W2,
                                               const float* __restrict__ b1) {
    __shared__ float Ws[H * H];  // 16 KB
    __shared__ float b1S[H];
    int tid = threadIdx.x;
#pragma unroll
    for (int i = 0; i < (H * H) / 256; ++i) Ws[tid + i * 256] = W2[tid + i * 256];
    if (tid < H) b1S[tid] = b1[tid];
    __syncthreads();

    int r  = blockIdx.x * 16 + (tid >> 4);
    int cg = (tid & 15) << 2;

    float a0 = 0.f, a1 = 0.f, a2 = 0.f, a3 = 0.f;
#pragma unroll
    for (int k4 = 0; k4 < H / 4; ++k4) {
        float4 hv = *(const float4*)&g_a1[(size_t)r * H + k4 * 4];
        float4 bb = *(const float4*)&b1S[k4 * 4];
        float h0 = fmaxf(hv.x + bb.x, 0.f);
        float h1 = fmaxf(hv.y + bb.y, 0.f);
        float h2 = fmaxf(hv.z + bb.z, 0.f);
        float h3 = fmaxf(hv.w + bb.w, 0.f);
        const float* wb = &Ws[(k4 * 4) * H + cg];
        float4 w0 = *(const float4*)(wb);
        float4 w1 = *(const float4*)(wb + H);
        float4 w2 = *(const float4*)(wb + 2 * H);
        float4 w3 = *(const float4*)(wb + 3 * H);
        a0 += h0 * w0.x; a1 += h0 * w0.y; a2 += h0 * w0.z; a3 += h0 * w0.w;
        a0 += h1 * w1.x; a1 += h1 * w1.y; a2 += h1 * w1.z; a3 += h1 * w1.w;
        a0 += h2 * w2.x; a1 += h2 * w2.y; a2 += h2 * w2.z; a3 += h2 * w2.w;
        a0 += h3 * w3.x; a1 += h3 * w3.y; a2 += h3 * w3.z; a3 += h3 * w3.w;
    }
    *(float4*)&g_h2[(size_t)r * H + cg] = make_float4(a0, a1, a2, a3);
}

// ---------------- self-loop init layer2: emb = dinv^2 * h2 (direct into d_out) ----------------
__global__ void k_self2(float* __restrict__ emb) {
    int i = blockIdx.x * blockDim.x + threadIdx.x;
    if (i < N_NODES * H) {
        float di = g_dinv[i >> 6];
        emb[i] = di * di * g_h2[i];
    }
}

// ---------------- edge scatter 2: emb[dst] += norm * h2[src] ----------------
__global__ void __launch_bounds__(256) k_edge2(float* __restrict__ agg) {
    int t = blockIdx.x * blockDim.x + threadIdx.x;
    int e = t >> 4;
    if (e >= N_EDGES) return;
    int lane = (t & 15) << 2;
    int s = g_src[e], d = g_dst[e];
    float nm = g_norm[e];
    float4 v = *(const float4*)(g_h2 + (size_t)s * H + lane);
    float* p = agg + (size_t)d * H + lane;
    asm volatile("red.global.add.v4.f32 [%0], {%1,%2,%3,%4};" ::
                 "l"(p), "f"(v.x * nm), "f"(v.y * nm), "f"(v.z * nm), "f"(v.w * nm)
                 : "memory");
}

// ---------------- final: emb += b2; logits = emb@Wc+bc; softmax; argmax ----------------
__global__ void __launch_bounds__(256) k_final(const float* __restrict__ b2,
                                               const float* __restrict__ Wc,
                                               const float* __restrict__ bc,
                                               float* __restrict__ out) {
    __shared__ float WcS[H * C];   // 10 KB
    __shared__ float bcS[C];
    __shared__ float b2S[H];
    __shared__ float eS[4][H];
    __shared__ float lS[4][C];
    __shared__ float mS[4];
    __shared__ float sS[4];

    int tid = threadIdx.x;
    for (int i = tid; i < H * C; i += 256) WcS[i] = Wc[i];
    if (tid < C) bcS[tid] = bc[tid];
    if (tid < H) b2S[tid] = b2[tid];
    __syncthreads();

    int ny = tid >> 6, k = tid & 63;
    int n = blockIdx.x * 4 + ny;

    const size_t embOff  = (size_t)N_NODES * C;
    const size_t softOff = embOff + (size_t)N_NODES * H;
    const size_t hardOff = softOff + (size_t)N_NODES * C;

    float* embp = out + embOff;
    float ev = embp[(size_t)n * H + k] + b2S[k];
    embp[(size_t)n * H + k] = ev;
    eS[ny][k] = ev;
    __syncthreads();

    if (k < C) {
        float acc = bcS[k];
#pragma unroll
        for (int kk = 0; kk < H; ++kk) acc += eS[ny][kk] * WcS[kk * C + k];
        lS[ny][k] = acc;
        out[(size_t)n * C + k] = acc;
    }
    __syncthreads();

    if (k == 0) {
        float m = lS[ny][0];
        int arg = 0;
#pragma unroll
        for (int c = 1; c < C; ++c) {
            float v = lS[ny][c];
            if (v > m) { m = v; arg = c; }
        }
        mS[ny] = m;
        out[hardOff + n] = (float)arg;
    }
    __syncthreads();

    float ex = 0.f;
    if (k < C) {
        ex = expf(lS[ny][k] - mS[ny]);
        lS[ny][k] = ex;
    }
    __syncthreads();

    if (k == 0) {
        float s = 0.f;
        for (int c = 0; c < C; ++c) s += lS[ny][c];
        sS[ny] = 1.0f / s;
    }
    __syncthreads();

    if (k < C) out[softOff + (size_t)n * C + k] = ex * sS[ny];
}

// ---------------- launch ----------------
extern "C" void kernel_launch(void* const* d_in, const int* in_sizes, int n_in,
                              void* d_out, int out_size) {
    const float* x  = (const float*)d_in[0];
    const void*  ei = d_in[1];
    const float* W1 = (const float*)d_in[2];
    const float* b1 = (const float*)d_in[3];
    const float* W2 = (const float*)d_in[4];
    const float* b2 = (const float*)d_in[5];
    const float* Wc = (const float*)d_in[6];
    const float* bc = (const float*)d_in[7];
    float* out = (float*)d_out;
    float* emb = out + (size_t)N_NODES * C;

    k_detect<<<1, 32>>>(ei);
    k_zero_deg<<<(N_NODES + 255) / 256, 256>>>();
    k_hist<<<(N_EDGES + 255) / 256, 256>>>(ei);
    k_dinv<<<(N_NODES + 255) / 256, 256>>>();
    k_prep<<<(N_EDGES + 255) / 256, 256>>>(ei);

    k_gemm1<<<N_NODES / 16, 256>>>(x, W1);
    k_self1<<<(N_NODES * H) / 256, 256>>>();
    k_edge1<<<(N_EDGES * 16) / 256, 256>>>();

    k_gemm2<<<N_NODES / 16, 256>>>(W2, b1);
    k_self2<<<(N_NODES * H) / 256, 256>>>(emb);
    k_edge2<<<(N_EDGES * 16) / 256, 256>>>(emb);

    k_final<<<N_NODES / 4, 256>>>(b2, Wc, bc, out);
}

// round 2
// speedup vs baseline: 1.3789x; 1.3789x over previous
#include <cuda_runtime.h>
#include <math.h>

#define N_NODES 100000
#define N_EDGES 1200000
#define F_IN 128
#define H 64
#define C 40
#define NB_SCAN 391   // ceil(100000/256)

// ---------------- scratch (device globals; no allocs allowed) ----------------
__device__ int   g_is64;
__device__ int   g_deg[N_NODES];
__device__ int   g_off[N_NODES];
__device__ int   g_cur[N_NODES];
__device__ int   g_bsum[NB_SCAN];
__device__ float g_dinv[N_NODES];
__device__ int   g_csrc[N_EDGES];
__device__ float g_h1[(size_t)N_NODES * H];   // x @ W1
__device__ float g_h2[(size_t)N_NODES * H];   // relu(agg1+b1) @ W2

// ---------------- int64-vs-int32 edge_index detection ----------------
__global__ void k_detect(const void* ei) {
    if (threadIdx.x == 0 && blockIdx.x == 0) {
        const long long* p = (const long long*)ei;
        int ok = 1;
        for (int i = 0; i < 64; ++i) {
            long long v = p[i];
            if (v < 0 || v >= N_NODES) { ok = 0; break; }
        }
        g_is64 = ok;
    }
}

__device__ __forceinline__ int load_idx(const void* ei, int pos, int which) {
    if (g_is64) return (int)((const long long*)ei)[(size_t)which * N_EDGES + pos];
    return ((const int*)ei)[(size_t)which * N_EDGES + pos];
}

// ---------------- degree ----------------
__global__ void k_zero_deg() {
    int i = blockIdx.x * blockDim.x + threadIdx.x;
    if (i < N_NODES) g_deg[i] = 0;
}

__global__ void k_hist(const void* __restrict__ ei) {
    int e = blockIdx.x * blockDim.x + threadIdx.x;
    if (e < N_EDGES) atomicAdd(&g_deg[load_idx(ei, e, 1)], 1);
}

// ---------------- exclusive scan of degrees (3 kernels) + dinv ----------------
__global__ void __launch_bounds__(256) k_scan1() {
    int i = blockIdx.x * 256 + threadIdx.x;
    int v = (i < N_NODES) ? g_deg[i] : 0;
    int lane = threadIdx.x & 31, w = threadIdx.x >> 5;
    int incl = v;
#pragma unroll
    for (int o = 1; o < 32; o <<= 1) {
        int t = __shfl_up_sync(0xffffffffu, incl, o);
        if (lane >= o) incl += t;
    }
    __shared__ int ws[8];
    if (lane == 31) ws[w] = incl;
    __syncthreads();
    if (w == 0 && lane < 8) {
        int t = ws[lane];
        int inc = t;
#pragma unroll
        for (int o = 1; o < 8; o <<= 1) {
            int u = __shfl_up_sync(0xffu, inc, o);
            if (lane >= o) inc += u;
        }
        ws[lane] = inc - t;  // exclusive warp base
    }
    __syncthreads();
    int excl = incl - v + ws[w];
    if (i < N_NODES) {
        g_off[i] = excl;
        g_dinv[i] = rsqrtf((float)(v + 1));  // +1 self-loop
    }
    if (threadIdx.x == 255) g_bsum[blockIdx.x] = excl + v;
}

__global__ void __launch_bounds__(512) k_scan2() {
    __shared__ int buf[512];
    int t = threadIdx.x;
    int v = (t < NB_SCAN) ? g_bsum[t] : 0;
    buf[t] = v;
    __syncthreads();
    for (int o = 1; o < 512; o <<= 1) {
        int u = (t >= o) ? buf[t - o] : 0;
        __syncthreads();
        buf[t] += u;
        __syncthreads();
    }
    if (t < NB_SCAN) g_bsum[t] = buf[t] - v;  // exclusive
}

__global__ void __launch_bounds__(256) k_scan3() {
    int i = blockIdx.x * 256 + threadIdx.x;
    if (i < N_NODES) {
        int o = g_off[i] + g_bsum[blockIdx.x];
        g_off[i] = o;
        g_cur[i] = o;
    }
}

// ---------------- CSR scatter (int atomics only) ----------------
__global__ void k_scatter(const void* __restrict__ ei) {
    int e = blockIdx.x * blockDim.x + threadIdx.x;
    if (e < N_EDGES) {
        int s = load_idx(ei, e, 0);
        int d = load_idx(ei, e, 1);
        int pos = atomicAdd(&g_cur[d], 1);
        g_csrc[pos] = s;
    }
}

// ---------------- GEMM1: g_h1 = x @ W1  (100000x128 @ 128x64) ----------------
__global__ void __launch_bounds__(256) k_gemm1(const float* __restrict__ x,
                                               const float* __restrict__ W1) {
    __shared__ float Ws[F_IN * H];  // 32 KB
    int tid = threadIdx.x;
#pragma unroll
    for (int i = 0; i < (F_IN * H) / 256; ++i) Ws[tid + i * 256] = W1[tid + i * 256];
    __syncthreads();

    int r  = blockIdx.x * 16 + (tid >> 4);
    int cg = (tid & 15) << 2;
    const float4* xr = reinterpret_cast<const float4*>(x + (size_t)r * F_IN);

    float a0 = 0.f, a1 = 0.f, a2 = 0.f, a3 = 0.f;
#pragma unroll
    for (int k4 = 0; k4 < F_IN / 4; ++k4) {
        float4 xv = xr[k4];
        const float* wb = &Ws[(k4 * 4) * H + cg];
        float4 w0 = *(const float4*)(wb);
        float4 w1 = *(const float4*)(wb + H);
        float4 w2 = *(const float4*)(wb + 2 * H);
        float4 w3 = *(const float4*)(wb + 3 * H);
        a0 += xv.x * w0.x; a1 += xv.x * w0.y; a2 += xv.x * w0.z; a3 += xv.x * w0.w;
        a0 += xv.y * w1.x; a1 += xv.y * w1.y; a2 += xv.y * w1.z; a3 += xv.y * w1.w;
        a0 += xv.z * w2.x; a1 += xv.z * w2.y; a2 += xv.z * w2.z; a3 += xv.z * w2.w;
        a0 += xv.w * w3.x; a1 += xv.w * w3.y; a2 += xv.w * w3.z; a3 += xv.w * w3.w;
    }
    *(float4*)&g_h1[(size_t)r * H + cg] = make_float4(a0, a1, a2, a3);
}

// ---------------- layer1: pull-aggregate h1 -> +b1,relu -> @W2 -> h2 ----------------
// one warp per node; 2 features per lane
__global__ void __launch_bounds__(256) k_layer1(const float* __restrict__ W2,
                                                const float* __restrict__ b1) {
    __shared__ float W2s[H * H];  // 16 KB
    __shared__ float b1s[H];
    __shared__ float aS[8][H];
    int tid = threadIdx.x;
#pragma unroll
    for (int i = 0; i < (H * H) / 256; ++i) W2s[tid + i * 256] = W2[tid + i * 256];
    if (tid < H) b1s[tid] = b1[tid];
    __syncthreads();

    int w = tid >> 5, lane = tid & 31;
    int n = blockIdx.x * 8 + w;
    int c = lane << 1;

    float di = g_dinv[n];
    int row = g_off[n], deg = g_deg[n];

    float2 acc = *(const float2*)&g_h1[(size_t)n * H + c];
    float sl = di * di;
    acc.x *= sl; acc.y *= sl;

    const int* ep = g_csrc + row;
    for (int j = 0; j < deg; ++j) {
        int s = ep[j];
        float nm = g_dinv[s] * di;
        float2 v = *(const float2*)&g_h1[(size_t)s * H + c];
        acc.x += nm * v.x;
        acc.y += nm * v.y;
    }

    float a0 = fmaxf(acc.x + b1s[c], 0.f);
    float a1 = fmaxf(acc.y + b1s[c + 1], 0.f);
    aS[w][c] = a0;
    aS[w][c + 1] = a1;
    __syncwarp();

    float o0 = 0.f, o1 = 0.f;
#pragma unroll
    for (int k = 0; k < H; ++k) {
        float av = aS[w][k];
        float2 wv = *(const float2*)&W2s[k * H + c];
        o0 += av * wv.x;
        o1 += av * wv.y;
    }
    *(float2*)&g_h2[(size_t)n * H + c] = make_float2(o0, o1);
}

// ---------------- layer2: pull-aggregate h2 -> +b2 -> emb, @Wc+bc -> logits,
//                  softmax -> soft, argmax -> hard.  one warp per node ----------------
__global__ void __launch_bounds__(256) k_layer2(const float* __restrict__ b2,
                                                const float* __restrict__ Wc,
                                                const float* __restrict__ bc,
                                                float* __restrict__ out) {
    __shared__ float WcS[H * C];  // 10.24 KB
    __shared__ float b2s[H];
    __shared__ float bcs[C];
    __shared__ float eS[8][H];
    int tid = threadIdx.x;
    for (int i = tid; i < H * C; i += 256) WcS[i] = Wc[i];
    if (tid < H) b2s[tid] = b2[tid];
    if (tid < C) bcs[tid] = bc[tid];
    __syncthreads();

    int w = tid >> 5, lane = tid & 31;
    int n = blockIdx.x * 8 + w;
    int c = lane << 1;

    const size_t embOff  = (size_t)N_NODES * C;
    const size_t softOff = embOff + (size_t)N_NODES * H;
    const size_t hardOff = softOff + (size_t)N_NODES * C;

    float di = g_dinv[n];
    int row = g_off[n], deg = g_deg[n];

    float2 acc = *(const float2*)&g_h2[(size_t)n * H + c];
    float sl = di * di;
    acc.x *= sl; acc.y *= sl;

    const int* ep = g_csrc + row;
    for (int j = 0; j < deg; ++j) {
        int s = ep[j];
        float nm = g_dinv[s] * di;
        float2 v = *(const float2*)&g_h2[(size_t)s * H + c];
        acc.x += nm * v.x;
        acc.y += nm * v.y;
    }
    acc.x += b2s[c];
    acc.y += b2s[c + 1];

    *(float2*)(out + embOff + (size_t)n * H + c) = acc;
    eS[w][c] = acc.x;
    eS[w][c + 1] = acc.y;
    __syncwarp();

    // logits: lane owns col lane; lanes 0..7 also own col lane+32
    float acc0 = bcs[lane];
    float acc1 = (lane < 8) ? bcs[lane + 32] : 0.f;
#pragma unroll
    for (int k = 0; k < H; ++k) {
        float ev = eS[w][k];
        acc0 += ev * WcS[k * C + lane];
        if (lane < 8) acc1 += ev * WcS[k * C + lane + 32];
    }
    out[(size_t)n * C + lane] = acc0;
    if (lane < 8) out[(size_t)n * C + lane + 32] = acc1;

    // argmax + max
    float mv = acc0;
    int   mi = lane;
    if (lane < 8 && acc1 > mv) { mv = acc1; mi = lane + 32; }
#pragma unroll
    for (int o = 16; o; o >>= 1) {
        float ov = __shfl_xor_sync(0xffffffffu, mv, o);
        int   oi = __shfl_xor_sync(0xffffffffu, mi, o);
        if (ov > mv || (ov == mv && oi < mi)) { mv = ov; mi = oi; }
    }
    if (lane == 0) out[hardOff + n] = (float)mi;

    // softmax
    float e0 = expf(acc0 - mv);
    float e1 = (lane < 8) ? expf(acc1 - mv) : 0.f;
    float s = e0 + e1;
#pragma unroll
    for (int o = 16; o; o >>= 1) s += __shfl_xor_sync(0xffffffffu, s, o);
    float inv = 1.0f / s;
    out[softOff + (size_t)n * C + lane] = e0 * inv;
    if (lane < 8) out[softOff + (size_t)n * C + lane + 32] = e1 * inv;
}

// ---------------- launch ----------------
extern "C" void kernel_launch(void* const* d_in, const int* in_sizes, int n_in,
                              void* d_out, int out_size) {
    const float* x  = (const float*)d_in[0];
    const void*  ei = d_in[1];
    const float* W1 = (const float*)d_in[2];
    const float* b1 = (const float*)d_in[3];
    const float* W2 = (const float*)d_in[4];
    const float* b2 = (const float*)d_in[5];
    const float* Wc = (const float*)d_in[6];
    const float* bc = (const float*)d_in[7];
    float* out = (float*)d_out;

    k_detect<<<1, 32>>>(ei);
    k_zero_deg<<<(N_NODES + 255) / 256, 256>>>();
    k_hist<<<(N_EDGES + 255) / 256, 256>>>(ei);
    k_scan1<<<NB_SCAN, 256>>>();
    k_scan2<<<1, 512>>>();
    k_scan3<<<NB_SCAN, 256>>>();
    k_scatter<<<(N_EDGES + 255) / 256, 256>>>(ei);

    k_gemm1<<<N_NODES / 16, 256>>>(x, W1);
    k_layer1<<<N_NODES / 8, 256>>>(W2, b1);
    k_layer2<<<N_NODES / 8, 256>>>(b2, Wc, bc, out);
}